// round 16
// baseline (speedup 1.0000x reference)
#include <cuda_runtime.h>
#include <cuda_fp16.h>
#include <cstdint>

#define D_DIM   50257
#define B_Q     64
#define K_A     4096
#define KNN     8
#define EPSF    1e-10f
#define LN2F    0.69314718055994530942f
#define MU      (-1.0f)              // global qlog mean: E[ln U(0,1)] = -1

#define DSPLIT  14
#define DTILE   64
#define STAGES  57                   // 14*57*64 = 51072 >= 50257
#define CHUNK_D (STAGES * DTILE)     // 3648
#define DPAD    (DSPLIT * CHUNK_D)   // 51072
#define NTILES  (DPAD / DTILE)       // 798
#define KTILE   128

// ---- static device scratch ----
// per 64-d tile: 8KB = 64 rows(k) x 128B(64 n fp16), 16B chunk c stored at c^(k&7)
__device__ __align__(16) unsigned short g_qB[NTILES * 4096];  // 6.5MB  (r = qlog - MU, fp16)
__device__ float g_cross[DSPLIT * B_Q * K_A];                 // 14.7MB partial  sum a_h*r_h
__device__ float g_self [DSPLIT * K_A];                       //        partial  sum a*(ln a - MU)

__device__ __forceinline__ uint32_t smem_u32(const void* p) {
    uint32_t a;
    asm("{ .reg .u64 t; cvta.to.shared.u64 t, %1; cvt.u32.u64 %0, t; }" : "=r"(a) : "l"(p));
    return a;
}

#define CP_ASYNC16(dst, src) asm volatile("cp.async.cg.shared.global [%0], [%1], 16;" :: "r"(dst), "l"(src))
#define CP_COMMIT()          asm volatile("cp.async.commit_group;" ::: "memory")
#define CP_WAIT0()           asm volatile("cp.async.wait_group 0;" ::: "memory")

#define LDSM_X4(r, a) \
    asm volatile("ldmatrix.sync.aligned.m8n8.x4.shared.b16 {%0,%1,%2,%3}, [%4];" \
        : "=r"((r)[0]),"=r"((r)[1]),"=r"((r)[2]),"=r"((r)[3]) : "r"(a))
#define LDSM_X4T(r, a) \
    asm volatile("ldmatrix.sync.aligned.m8n8.x4.trans.shared.b16 {%0,%1,%2,%3}, [%4];" \
        : "=r"((r)[0]),"=r"((r)[1]),"=r"((r)[2]),"=r"((r)[3]) : "r"(a))

#define MMA16816F16(c, a, b0, b1) \
    asm volatile("mma.sync.aligned.m16n8k16.row.col.f32.f16.f16.f32 " \
        "{%0,%1,%2,%3}, {%4,%5,%6,%7}, {%8,%9}, {%0,%1,%2,%3};" \
        : "+f"((c)[0]),"+f"((c)[1]),"+f"((c)[2]),"+f"((c)[3]) \
        : "r"((a)[0]),"r"((a)[1]),"r"((a)[2]),"r"((a)[3]), "r"(b0),"r"(b1))

// pack two fp32 -> one fp16x2 word (lo = x, hi = y)
__device__ __forceinline__ uint32_t f16x2pack(float x, float y) {
    uint32_t r;
    asm("cvt.rn.f16x2.f32 %0, %1, %2;" : "=r"(r) : "f"(y), "f"(x));
    return r;
}

// ---------------- Kernel A: r = ln(q+eps) - MU -> fp16 tiles (64 k x 64 n, chunk^ (k&7)) ----------------
#define QPAD 72
__global__ void __launch_bounds__(256)
qlog_kernel(const float* __restrict__ q) {
    __shared__ __align__(16) unsigned short sr[64 * QPAD];
    const int t    = blockIdx.x;
    const int lane = threadIdx.x & 31;
    const int w    = threadIdx.x >> 5;
#pragma unroll
    for (int h = 0; h < 2; ++h) {
        const int d = t * DTILE + h * 32 + lane;
        const bool v = d < D_DIM;
#pragma unroll
        for (int i = 0; i < 8; ++i) {
            const int b = w * 8 + i;
            float r = 0.f;
            if (v) r = __log2f(q[(size_t)b * D_DIM + d] + EPSF) * LN2F - MU;  // coalesced reads
            sr[(h * 32 + lane) * QPAD + b] = __half_as_ushort(__float2half(r));
        }
    }
    __syncthreads();
    // repack: 64 rows x 8 chunks of 16B; thread handles rows tid>>3 and tid>>3 + 32
    uint4* tb = reinterpret_cast<uint4*>(g_qB + (size_t)t * 4096);
    const int cs = threadIdx.x & 7;
#pragma unroll
    for (int hh = 0; hh < 2; ++hh) {
        const int k = (threadIdx.x >> 3) + hh * 32;
        const int c = cs ^ (k & 7);
        tb[k * 8 + cs] = *reinterpret_cast<const uint4*>(sr + k * QPAD + c * 8);
    }
}

// ---------------- Kernel B: single-chain fp16 GEMM (A_h * r_h) + fused self-term, 3 CTAs/SM ----------------
// smem: A [2 buf][128 r][128B] at 0 (buf 16KB), B [2 buf][64 k][128B] at 32768 (buf 8KB). 48KB total.
// Warp grid 4x2 (warp tile 32M x 32N). A swizzle: 16B chunk c stored at c^(row&7).
__global__ void __launch_bounds__(256, 3)
gemm_kernel(const float* __restrict__ anchor) {
    __shared__ __align__(128) char smem[49152];
    const uint32_t sA = smem_u32(smem);
    const uint32_t sB = sA + 32768;

    const int tid  = threadIdx.x;
    const int lane = tid & 31;
    const int wid  = tid >> 5;
    const int wm   = wid >> 1;        // 0..3 : 32-row M tile
    const int wn   = wid & 1;         // 0..1 : 32-col N tile
    const int kb   = blockIdx.x * KTILE;
    const int cI   = blockIdx.y;
    const int dbase = cI * CHUNK_D;

    // ldmatrix lane constants
    const int rowA = lane & 15;
    const int cA   = lane >> 4;
    const int kB   = lane & 15;
    const int cB   = lane >> 4;
    const int swzB = lane & 7;

    float acc[2][4][4];               // [mi][nh][frag]
#pragma unroll
    for (int mi = 0; mi < 2; ++mi)
#pragma unroll
        for (int nh = 0; nh < 4; ++nh)
#pragma unroll
            for (int r = 0; r < 4; ++r) acc[mi][nh][r] = 0.f;

    float selfAcc[16];                // per owned row (wid*16 + i), this lane's d-slice
#pragma unroll
    for (int i = 0; i < 16; ++i) selfAcc[i] = 0.f;

    float2 va[8];                     // one row-half in flight

    // loader: warp owns rows wid*16..+15; lane l covers float2 l (d = 2l..2l+1) of each row
    auto loadAh = [&](int s, int half) {
        const int d0 = dbase + s * DTILE + 2 * lane;
        const bool vx = d0 < D_DIM;
        const bool vy = d0 + 1 < D_DIM;
#pragma unroll
        for (int i = 0; i < 8; ++i) {
            const float* p = anchor + (size_t)(kb + wid * 16 + half * 8 + i) * D_DIM + d0;
            va[i].x = vx ? __ldg(p)     : 0.f;
            va[i].y = vy ? __ldg(p + 1) : 0.f;
        }
    };
    auto storeAh = [&](int buf, int half) {
#pragma unroll
        for (int i = 0; i < 8; ++i) {
            const int r = wid * 16 + half * 8 + i;
            // self' = a * (ln(a+eps) - MU); exact fp32 (compiler: MUFU + 2 FFMA per element)
            selfAcc[half * 8 + i] += va[i].x * (__log2f(va[i].x + EPSF) * LN2F - MU)
                                   + va[i].y * (__log2f(va[i].y + EPSF) * LN2F - MU);
            uint32_t ph = f16x2pack(va[i].x, va[i].y);
            uint32_t byte = (uint32_t)r * 128 + ((((uint32_t)lane >> 2) ^ ((uint32_t)r & 7)) << 4)
                          + ((uint32_t)lane & 3) * 4;
            *(uint32_t*)(smem + buf * 16384 + byte) = ph;   // all lanes same row -> 32 banks
        }
    };
    auto issueB = [&](int s, int buf) {
        const char* src = reinterpret_cast<const char*>(g_qB) + (size_t)(cI * STAGES + s) * 8192;
        uint32_t dst = sB + buf * 8192 + tid * 16;
        CP_ASYNC16(dst, src + tid * 16);
        CP_ASYNC16(dst + 4096, src + tid * 16 + 4096);
    };

    // compute for one k16 group kh (0..3) of buffer buf
    auto computeKh = [&](int buf, int kh) {
        const uint32_t aBase = sA + buf * 16384;
        const uint32_t bBase = sB + buf * 8192;
        uint32_t bh[2][4], ah[2][4];
#pragma unroll
        for (int nc = 0; nc < 2; ++nc) {
            uint32_t addr = bBase + (uint32_t)(kh * 16 + kB) * 128
                          + (uint32_t)(((wn * 4 + nc * 2 + cB) ^ swzB) << 4);
            LDSM_X4T(bh[nc], addr);
        }
#pragma unroll
        for (int mi = 0; mi < 2; ++mi) {
            const int R = wm * 32 + mi * 16;
            const int rr = R + rowA;
            uint32_t addr = aBase + (uint32_t)rr * 128
                          + (uint32_t)(((kh * 2 + cA) ^ (rr & 7)) << 4);
            LDSM_X4(ah[mi], addr);
        }
#pragma unroll
        for (int mi = 0; mi < 2; ++mi)
#pragma unroll
            for (int nc = 0; nc < 2; ++nc) {
                MMA16816F16(acc[mi][2 * nc],     ah[mi], bh[nc][0], bh[nc][1]);
                MMA16816F16(acc[mi][2 * nc + 1], ah[mi], bh[nc][2], bh[nc][3]);
            }
    };

    // prologue: fill buffer 0
    loadAh(0, 0); storeAh(0, 0);
    loadAh(0, 1); storeAh(0, 1);
    issueB(0, 0);
    CP_COMMIT();
    CP_WAIT0();
    __syncthreads();

    for (int s = 0; s < STAGES; ++s) {
        const int buf = s & 1;
        const bool more = (s + 1 < STAGES);
        if (more) {
            issueB(s + 1, buf ^ 1);
            CP_COMMIT();
            loadAh(s + 1, 0);
        }
        computeKh(buf, 0);
        computeKh(buf, 1);
        if (more) {
            storeAh(buf ^ 1, 0);
            loadAh(s + 1, 1);
        }
        computeKh(buf, 2);
        computeKh(buf, 3);
        if (more) storeAh(buf ^ 1, 1);
        CP_WAIT0();
        __syncthreads();
    }

    // ---- self-term: reduce over all 32 lanes sharing each row ----
#pragma unroll
    for (int i = 0; i < 16; ++i) {
        float v = selfAcc[i];
        v += __shfl_xor_sync(0xffffffffu, v, 16);
        v += __shfl_xor_sync(0xffffffffu, v, 8);
        v += __shfl_xor_sync(0xffffffffu, v, 4);
        v += __shfl_xor_sync(0xffffffffu, v, 2);
        v += __shfl_xor_sync(0xffffffffu, v, 1);
        if (lane == 0)
            g_self[cI * K_A + kb + wid * 16 + i] = v;
    }

    // ---- epilogue: transpose through smem, coalesced g_cross stores ----
    float* Csm = reinterpret_cast<float*>(smem);   // [64 q][128 m] = 32KB
    const int g   = lane >> 2;
    const int tig = lane & 3;
#pragma unroll
    for (int mi = 0; mi < 2; ++mi) {
        const int r0 = wm * 32 + mi * 16 + g;
#pragma unroll
        for (int nh = 0; nh < 4; ++nh) {
            const int col = wn * 32 + nh * 8 + tig * 2;
            Csm[(col    ) * 128 + r0    ] = acc[mi][nh][0];
            Csm[(col + 1) * 128 + r0    ] = acc[mi][nh][1];
            Csm[(col    ) * 128 + r0 + 8] = acc[mi][nh][2];
            Csm[(col + 1) * 128 + r0 + 8] = acc[mi][nh][3];
        }
    }
    __syncthreads();
    {
        const int qq = tid >> 2;
        const int mb = (tid & 3) * 32;
        const float4* src = reinterpret_cast<const float4*>(Csm + qq * 128 + mb);
        float4* dst = reinterpret_cast<float4*>(g_cross + ((size_t)(cI * B_Q + qq)) * K_A + kb + mb);
#pragma unroll
        for (int j = 0; j < 8; ++j) dst[j] = src[j];
    }
}

// ---------------- Kernel C: fp64 combine + top-8 argmin + majority vote ----------------
__global__ void __launch_bounds__(256)
topk_kernel(const int* __restrict__ label, float* __restrict__ out) {
    __shared__ double kl[K_A];
    __shared__ double rv[256];
    __shared__ int    ri[256];
    const int b   = blockIdx.x;
    const int tid = threadIdx.x;

    for (int k = tid; k < K_A; k += 256) {
        double s = 0.0;
#pragma unroll
        for (int c = 0; c < DSPLIT; ++c)
            s += (double)g_self[c * K_A + k]
               - (double)g_cross[((size_t)(c * B_Q + b)) * K_A + k];
        kl[k] = s;   // = D * kl[b][k]  (self' and cross_r absorb the -MU centering exactly)
    }
    __syncthreads();

    int cnt1 = 0;
    for (int r = 0; r < KNN; ++r) {
        double bv = 1e300; int bi = K_A - 1;
        for (int k = tid; k < K_A; k += 256) {
            double v = kl[k];
            if (v < bv) { bv = v; bi = k; }
        }
        rv[tid] = bv; ri[tid] = bi;
        __syncthreads();
        for (int off = 128; off > 0; off >>= 1) {
            if (tid < off) {
                double v = rv[tid + off]; int i2 = ri[tid + off];
                if (v < rv[tid] || (v == rv[tid] && i2 < ri[tid])) { rv[tid] = v; ri[tid] = i2; }
            }
            __syncthreads();
        }
        int sel = ri[0];
        if (sel < 0)    sel = 0;
        if (sel >= K_A) sel = K_A - 1;
        cnt1 += label[sel];
        if (tid == 0) kl[sel] = 1e300;
        __syncthreads();
    }
    if (tid == 0) out[b] = (cnt1 > KNN / 2) ? 1.0f : 0.0f;
}

extern "C" void kernel_launch(void* const* d_in, const int* in_sizes, int n_in,
                              void* d_out, int out_size) {
    (void)in_sizes; (void)n_in; (void)out_size;
    const float* query  = (const float*)d_in[0];
    const float* anchor = (const float*)d_in[1];
    const int*   label  = (const int*)d_in[2];
    float* out = (float*)d_out;

    qlog_kernel<<<NTILES, 256>>>(query);
    dim3 g(K_A / KTILE, DSPLIT);
    gemm_kernel<<<g, 256>>>(anchor);
    topk_kernel<<<B_Q, 256>>>(label, out);
}

// round 17
// speedup vs baseline: 1.2059x; 1.2059x over previous
#include <cuda_runtime.h>
#include <cuda_fp16.h>
#include <cstdint>

#define D_DIM   50257
#define B_Q     64
#define K_A     4096
#define KNN     8
#define EPSF    1e-10f
#define LN2F    0.69314718055994530942f
#define MU      (-1.0f)              // global qlog mean: E[ln U(0,1)] = -1

#define DSPLIT  9
#define DTILE   64
#define STAGES  88                   // 9*88*64 = 50688 >= 50257
#define CHUNK_D (STAGES * DTILE)     // 5632
#define DPAD    (DSPLIT * CHUNK_D)   // 50688
#define NTILES  (DPAD / DTILE)       // 792
#define KTILE   128

// ---- static device scratch ----
// per 64-d tile: 8KB = 64 rows(k) x 128B(64 n fp16), 16B chunk c stored at c^(k&7)
// k-permutation: row k=2p <-> d0+p, k=2p+1 <-> d0+32+p (A side uses the same order)
__device__ __align__(16) unsigned short g_qB[NTILES * 4096];  // 6.4MB  (r = qlog - MU, fp16)
__device__ float g_cross[DSPLIT * B_Q * K_A];                 // 9.4MB  partial  sum a_h*r_h
__device__ float g_self [DSPLIT * K_A];                       //        partial  sum a*(ln a - MU)

__device__ __forceinline__ uint32_t smem_u32(const void* p) {
    uint32_t a;
    asm("{ .reg .u64 t; cvta.to.shared.u64 t, %1; cvt.u32.u64 %0, t; }" : "=r"(a) : "l"(p));
    return a;
}

#define CP_ASYNC16(dst, src) asm volatile("cp.async.cg.shared.global [%0], [%1], 16;" :: "r"(dst), "l"(src))
#define CP_COMMIT()          asm volatile("cp.async.commit_group;" ::: "memory")
#define CP_WAIT0()           asm volatile("cp.async.wait_group 0;" ::: "memory")

#define LDSM_X4(r, a) \
    asm volatile("ldmatrix.sync.aligned.m8n8.x4.shared.b16 {%0,%1,%2,%3}, [%4];" \
        : "=r"((r)[0]),"=r"((r)[1]),"=r"((r)[2]),"=r"((r)[3]) : "r"(a))
#define LDSM_X4T(r, a) \
    asm volatile("ldmatrix.sync.aligned.m8n8.x4.trans.shared.b16 {%0,%1,%2,%3}, [%4];" \
        : "=r"((r)[0]),"=r"((r)[1]),"=r"((r)[2]),"=r"((r)[3]) : "r"(a))

#define MMA16816F16(c, a, b0, b1) \
    asm volatile("mma.sync.aligned.m16n8k16.row.col.f32.f16.f16.f32 " \
        "{%0,%1,%2,%3}, {%4,%5,%6,%7}, {%8,%9}, {%0,%1,%2,%3};" \
        : "+f"((c)[0]),"+f"((c)[1]),"+f"((c)[2]),"+f"((c)[3]) \
        : "r"((a)[0]),"r"((a)[1]),"r"((a)[2]),"r"((a)[3]), "r"(b0),"r"(b1))

// pack two fp32 -> one fp16x2 word (lo = x, hi = y)
__device__ __forceinline__ uint32_t f16x2pack(float x, float y) {
    uint32_t r;
    asm("cvt.rn.f16x2.f32 %0, %1, %2;" : "=r"(r) : "f"(y), "f"(x));
    return r;
}

// ---------------- Kernel A: r = ln(q+eps) - MU -> fp16 tiles, permuted k-order ----------------
#define QPAD 72
__global__ void __launch_bounds__(256)
qlog_kernel(const float* __restrict__ q) {
    __shared__ __align__(16) unsigned short sr[64 * QPAD];
    const int t    = blockIdx.x;
    const int lane = threadIdx.x & 31;
    const int w    = threadIdx.x >> 5;
#pragma unroll
    for (int h = 0; h < 2; ++h) {
        const int d = t * DTILE + h * 32 + lane;   // position p = lane, half h -> k = 2*lane + h
        const bool v = d < D_DIM;
#pragma unroll
        for (int i = 0; i < 8; ++i) {
            const int b = w * 8 + i;
            float r = 0.f;
            if (v) r = __log2f(q[(size_t)b * D_DIM + d] + EPSF) * LN2F - MU;  // coalesced reads
            sr[(2 * lane + h) * QPAD + b] = __half_as_ushort(__float2half(r));
        }
    }
    __syncthreads();
    // repack: 64 rows x 8 chunks of 16B; thread handles rows tid>>3 and tid>>3 + 32
    uint4* tb = reinterpret_cast<uint4*>(g_qB + (size_t)t * 4096);
    const int cs = threadIdx.x & 7;
#pragma unroll
    for (int hh = 0; hh < 2; ++hh) {
        const int k = (threadIdx.x >> 3) + hh * 32;
        const int c = cs ^ (k & 7);
        tb[k * 8 + cs] = *reinterpret_cast<const uint4*>(sr + k * QPAD + c * 8);
    }
}

// ---------------- Kernel B: single-chain fp16 GEMM (A_h * r_h) + fused self-term ----------------
// smem: A [2 buf][128 r][128B] at 0 (buf 16KB), B [2 buf][64 k][128B] at 32768 (buf 8KB). 48KB total.
// Warp grid 4x2 (warp tile 32M x 32N). A swizzle: 16B chunk c stored at c^(row&7).
// A loader uses the permuted k-order: lane l packs (d0+l, d0+32+l) -> k-pair (2l, 2l+1).
__global__ void __launch_bounds__(256, 2)
gemm_kernel(const float* __restrict__ anchor) {
    __shared__ __align__(128) char smem[49152];
    const uint32_t sA = smem_u32(smem);
    const uint32_t sB = sA + 32768;

    const int tid  = threadIdx.x;
    const int lane = tid & 31;
    const int wid  = tid >> 5;
    const int wm   = wid >> 1;        // 0..3 : 32-row M tile
    const int wn   = wid & 1;         // 0..1 : 32-col N tile
    const int kb   = blockIdx.x * KTILE;
    const int cI   = blockIdx.y;
    const int dbase = cI * CHUNK_D;

    // ldmatrix lane constants
    const int rowA = lane & 15;
    const int cA   = lane >> 4;
    const int kB   = lane & 15;
    const int cB   = lane >> 4;
    const int swzB = lane & 7;

    float acc[2][4][4];               // [mi][nh][frag]
#pragma unroll
    for (int mi = 0; mi < 2; ++mi)
#pragma unroll
        for (int nh = 0; nh < 4; ++nh)
#pragma unroll
            for (int r = 0; r < 4; ++r) acc[mi][nh][r] = 0.f;

    float selfAcc[16];                // per owned row (wid*16 + i), this lane's d-slice
#pragma unroll
    for (int i = 0; i < 16; ++i) selfAcc[i] = 0.f;

    float2 va[8];                     // one row-half in flight: (d0+lane, d0+32+lane)

    // loader: warp owns rows wid*16..+15; lane l reads d0+l and d0+32+l (fully coalesced LDGs)
    auto loadAh = [&](int s, int half) {
        const int d0 = dbase + s * DTILE;
        const bool vx = (d0 + lane)      < D_DIM;
        const bool vy = (d0 + 32 + lane) < D_DIM;
#pragma unroll
        for (int i = 0; i < 8; ++i) {
            const float* p = anchor + (size_t)(kb + wid * 16 + half * 8 + i) * D_DIM + d0 + lane;
            va[i].x = vx ? __ldg(p)      : 0.f;   // 128B contiguous per warp-LDG
            va[i].y = vy ? __ldg(p + 32) : 0.f;   // 128B contiguous per warp-LDG
        }
    };
    auto storeAh = [&](int buf, int half) {
#pragma unroll
        for (int i = 0; i < 8; ++i) {
            const int r = wid * 16 + half * 8 + i;
            // self' = a * (ln(a+eps) - MU); exact fp32
            selfAcc[half * 8 + i] += va[i].x * (__log2f(va[i].x + EPSF) * LN2F - MU)
                                   + va[i].y * (__log2f(va[i].y + EPSF) * LN2F - MU);
            uint32_t ph = f16x2pack(va[i].x, va[i].y);    // k-pair (2*lane, 2*lane+1)
            uint32_t byte = (uint32_t)r * 128 + ((((uint32_t)lane >> 2) ^ ((uint32_t)r & 7)) << 4)
                          + ((uint32_t)lane & 3) * 4;
            *(uint32_t*)(smem + buf * 16384 + byte) = ph;   // all lanes same row -> 32 banks
        }
    };
    auto issueB = [&](int s, int buf) {
        const char* src = reinterpret_cast<const char*>(g_qB) + (size_t)(cI * STAGES + s) * 8192;
        uint32_t dst = sB + buf * 8192 + tid * 16;
        CP_ASYNC16(dst, src + tid * 16);
        CP_ASYNC16(dst + 4096, src + tid * 16 + 4096);
    };

    // compute for one k16 group kh (0..3) of buffer buf
    auto computeKh = [&](int buf, int kh) {
        const uint32_t aBase = sA + buf * 16384;
        const uint32_t bBase = sB + buf * 8192;
        uint32_t bh[2][4], ah[2][4];
#pragma unroll
        for (int nc = 0; nc < 2; ++nc) {
            uint32_t addr = bBase + (uint32_t)(kh * 16 + kB) * 128
                          + (uint32_t)(((wn * 4 + nc * 2 + cB) ^ swzB) << 4);
            LDSM_X4T(bh[nc], addr);
        }
#pragma unroll
        for (int mi = 0; mi < 2; ++mi) {
            const int R = wm * 32 + mi * 16;
            const int rr = R + rowA;
            uint32_t addr = aBase + (uint32_t)rr * 128
                          + (uint32_t)(((kh * 2 + cA) ^ (rr & 7)) << 4);
            LDSM_X4(ah[mi], addr);
        }
#pragma unroll
        for (int mi = 0; mi < 2; ++mi)
#pragma unroll
            for (int nc = 0; nc < 2; ++nc) {
                MMA16816F16(acc[mi][2 * nc],     ah[mi], bh[nc][0], bh[nc][1]);
                MMA16816F16(acc[mi][2 * nc + 1], ah[mi], bh[nc][2], bh[nc][3]);
            }
    };

    // prologue: fill buffer 0
    loadAh(0, 0); storeAh(0, 0);
    loadAh(0, 1); storeAh(0, 1);
    issueB(0, 0);
    CP_COMMIT();
    CP_WAIT0();
    __syncthreads();

    for (int s = 0; s < STAGES; ++s) {
        const int buf = s & 1;
        const bool more = (s + 1 < STAGES);
        if (more) {
            issueB(s + 1, buf ^ 1);
            CP_COMMIT();
            loadAh(s + 1, 0);
        }
        computeKh(buf, 0);
        computeKh(buf, 1);
        if (more) {
            storeAh(buf ^ 1, 0);
            loadAh(s + 1, 1);
        }
        computeKh(buf, 2);
        computeKh(buf, 3);
        if (more) storeAh(buf ^ 1, 1);
        CP_WAIT0();
        __syncthreads();
    }

    // ---- self-term: reduce over all 32 lanes sharing each row ----
#pragma unroll
    for (int i = 0; i < 16; ++i) {
        float v = selfAcc[i];
        v += __shfl_xor_sync(0xffffffffu, v, 16);
        v += __shfl_xor_sync(0xffffffffu, v, 8);
        v += __shfl_xor_sync(0xffffffffu, v, 4);
        v += __shfl_xor_sync(0xffffffffu, v, 2);
        v += __shfl_xor_sync(0xffffffffu, v, 1);
        if (lane == 0)
            g_self[cI * K_A + kb + wid * 16 + i] = v;
    }

    // ---- epilogue: transpose through smem, coalesced g_cross stores ----
    float* Csm = reinterpret_cast<float*>(smem);   // [64 q][128 m] = 32KB
    const int g   = lane >> 2;
    const int tig = lane & 3;
#pragma unroll
    for (int mi = 0; mi < 2; ++mi) {
        const int r0 = wm * 32 + mi * 16 + g;
#pragma unroll
        for (int nh = 0; nh < 4; ++nh) {
            const int col = wn * 32 + nh * 8 + tig * 2;
            Csm[(col    ) * 128 + r0    ] = acc[mi][nh][0];
            Csm[(col + 1) * 128 + r0    ] = acc[mi][nh][1];
            Csm[(col    ) * 128 + r0 + 8] = acc[mi][nh][2];
            Csm[(col + 1) * 128 + r0 + 8] = acc[mi][nh][3];
        }
    }
    __syncthreads();
    {
        const int qq = tid >> 2;
        const int mb = (tid & 3) * 32;
        const float4* src = reinterpret_cast<const float4*>(Csm + qq * 128 + mb);
        float4* dst = reinterpret_cast<float4*>(g_cross + ((size_t)(cI * B_Q + qq)) * K_A + kb + mb);
#pragma unroll
        for (int j = 0; j < 8; ++j) dst[j] = src[j];
    }
}

// ---------------- Kernel C: fp64 combine + top-8 argmin + majority vote ----------------
__global__ void __launch_bounds__(256)
topk_kernel(const int* __restrict__ label, float* __restrict__ out) {
    __shared__ double kl[K_A];
    __shared__ double rv[256];
    __shared__ int    ri[256];
    const int b   = blockIdx.x;
    const int tid = threadIdx.x;

    for (int k = tid; k < K_A; k += 256) {
        double s = 0.0;
#pragma unroll
        for (int c = 0; c < DSPLIT; ++c)
            s += (double)g_self[c * K_A + k]
               - (double)g_cross[((size_t)(c * B_Q + b)) * K_A + k];
        kl[k] = s;   // = D * kl[b][k]  (self' and cross_r absorb the -MU centering exactly)
    }
    __syncthreads();

    int cnt1 = 0;
    for (int r = 0; r < KNN; ++r) {
        double bv = 1e300; int bi = K_A - 1;
        for (int k = tid; k < K_A; k += 256) {
            double v = kl[k];
            if (v < bv) { bv = v; bi = k; }
        }
        rv[tid] = bv; ri[tid] = bi;
        __syncthreads();
        for (int off = 128; off > 0; off >>= 1) {
            if (tid < off) {
                double v = rv[tid + off]; int i2 = ri[tid + off];
                if (v < rv[tid] || (v == rv[tid] && i2 < ri[tid])) { rv[tid] = v; ri[tid] = i2; }
            }
            __syncthreads();
        }
        int sel = ri[0];
        if (sel < 0)    sel = 0;
        if (sel >= K_A) sel = K_A - 1;
        cnt1 += label[sel];
        if (tid == 0) kl[sel] = 1e300;
        __syncthreads();
    }
    if (tid == 0) out[b] = (cnt1 > KNN / 2) ? 1.0f : 0.0f;
}

extern "C" void kernel_launch(void* const* d_in, const int* in_sizes, int n_in,
                              void* d_out, int out_size) {
    (void)in_sizes; (void)n_in; (void)out_size;
    const float* query  = (const float*)d_in[0];
    const float* anchor = (const float*)d_in[1];
    const int*   label  = (const int*)d_in[2];
    float* out = (float*)d_out;

    qlog_kernel<<<NTILES, 256>>>(query);
    dim3 g(K_A / KTILE, DSPLIT);
    gemm_kernel<<<g, 256>>>(anchor);
    topk_kernel<<<B_Q, 256>>>(label, out);
}